// round 16
// baseline (speedup 1.0000x reference)
#include <cuda_runtime.h>
#include <math.h>
#include <stdint.h>

#define Bb 4
#define Nn 2048
#define Dd 256
#define Hh 4
#define HDd 64
#define M2 (2*Bb*Nn)
#define BND ((size_t)Bb*Nn*Dd)

// ---------------- static scratch ----------------
__device__ float g_x  [(size_t)M2*Dd];
__device__ float g_xr [(size_t)M2*Dd];
__device__ float g_qkv[(size_t)M2*3*Dd];
__device__ float g_q  [(size_t)2*Bb*Hh*Nn*HDd];
__device__ float g_k  [(size_t)2*Bb*Hh*Nn*HDd];
__device__ float g_v  [(size_t)2*Bb*Hh*Nn*HDd];
__device__ float g_tmp[(size_t)M2*Dd];
__device__ float g_h  [(size_t)M2*2*Dd];
// pre-rounded weights
__device__ float w_qkv [768*256];
__device__ float w_out [256*256];
__device__ float w_s1  [512*512];
__device__ float w_s2  [256*512];
__device__ float w_cqkv[512*256];
__device__ float w_co  [256*256];
__device__ float w_c1  [512*512];
__device__ float w_c2  [256*512];

__device__ __forceinline__ float tf32f(float x){
    float y; asm("cvt.rna.tf32.f32 %0, %1;" : "=f"(y) : "f"(x)); return y;
}

// ---------------- cp.async helpers ----------------
__device__ __forceinline__ void cpa16(uint32_t s, const void* g){
    asm volatile("cp.async.cg.shared.global [%0], [%1], 16;\n" :: "r"(s), "l"(g));
}
__device__ __forceinline__ void cpa_commit(){ asm volatile("cp.async.commit_group;\n"); }
template<int N> __device__ __forceinline__ void cpa_wait(){
    asm volatile("cp.async.wait_group %0;\n" :: "n"(N));
}
__device__ __forceinline__ uint32_t smem_u32(const void* p){
    uint32_t a;
    asm("{ .reg .u64 t; cvta.to.shared.u64 t, %1; cvt.u32.u64 %0, t; }" : "=r"(a) : "l"(p));
    return a;
}

// ---------------- mma.sync m16n8k8 tf32 ----------------
__device__ __forceinline__ void mma_tf32(float* c, const float* a, const float* b){
    asm volatile(
      "mma.sync.aligned.m16n8k8.row.col.f32.tf32.tf32.f32 "
      "{%0,%1,%2,%3},{%4,%5,%6,%7},{%8,%9},{%0,%1,%2,%3};\n"
      : "+f"(c[0]),"+f"(c[1]),"+f"(c[2]),"+f"(c[3])
      : "r"(__float_as_uint(a[0])),"r"(__float_as_uint(a[1])),
        "r"(__float_as_uint(a[2])),"r"(__float_as_uint(a[3])),
        "r"(__float_as_uint(b[0])),"r"(__float_as_uint(b[1])));
}

// ---------------- NT tf32 GEMM (unchanged from R10) ----------------
#define GLD 24
#define MG_SMEM (3*128*GLD*2*4)
__global__ void __launch_bounds__(128,2)
mgemm(const float* __restrict__ A, const float* __restrict__ A2, int lda,
      const float* __restrict__ W, int ldb,
      float* __restrict__ C, int ldc,
      const float* __restrict__ bias, const float* __restrict__ bias2,
      const float* __restrict__ Res, int ldr,
      int K, int round_out, float* __restrict__ Cr)
{
    extern __shared__ float dsm[];
    float (*As)[128][GLD] = reinterpret_cast<float(*)[128][GLD]>(dsm);
    float (*Bs)[128][GLD] = reinterpret_cast<float(*)[128][GLD]>(dsm + 3*128*GLD);

    const int bm = blockIdx.y*128, bn = blockIdx.x*128;
    const int tid = threadIdx.x, warp = tid>>5, lane = tid&31;
    const int wm = warp>>1, wn = warp&1;
    const int gq = lane>>2, tq = lane&3;

    float acc[4][8][4];
    #pragma unroll
    for (int m=0;m<4;m++)
        #pragma unroll
        for (int n=0;n<8;n++){
            acc[m][n][0]=0.f; acc[m][n][1]=0.f; acc[m][n][2]=0.f; acc[m][n][3]=0.f;
        }

    auto ld_tile = [&](int st, int k0){
        const float* Ab; int ka;
        if (A2 && k0 >= 256){ Ab = A2; ka = k0 - 256; } else { Ab = A; ka = k0; }
        #pragma unroll
        for (int i=0;i<4;i++){
            int id = tid + i*128;
            int row = id>>2, c4 = id&3;
            cpa16(smem_u32(&As[st][row][c4*4]), Ab + (size_t)(bm+row)*((A2)?256:lda) + ka + c4*4);
        }
        #pragma unroll
        for (int i=0;i<4;i++){
            int id = tid + i*128;
            int row = id>>2, c4 = id&3;
            cpa16(smem_u32(&Bs[st][row][c4*4]), W + (size_t)(bn+row)*ldb + k0 + c4*4);
        }
        cpa_commit();
    };

    const int KT = K/16;
    ld_tile(0, 0);
    ld_tile(1, 16);

    for (int kt=0; kt<KT; kt++){
        const int buf = kt%3;
        if (kt+1 < KT) cpa_wait<1>(); else cpa_wait<0>();
        __syncthreads();
        if (kt+2 < KT) ld_tile((kt+2)%3, (kt+2)*16);
        #pragma unroll
        for (int ks=0; ks<16; ks+=8){
            float a[4][4], b[8][2];
            #pragma unroll
            for (int m=0;m<4;m++){
                float2 a02 = *reinterpret_cast<const float2*>(&As[buf][wm*64 + m*16 + gq    ][ks + 2*tq]);
                float2 a13 = *reinterpret_cast<const float2*>(&As[buf][wm*64 + m*16 + gq + 8][ks + 2*tq]);
                a[m][0]=a02.x; a[m][2]=a02.y; a[m][1]=a13.x; a[m][3]=a13.y;
            }
            #pragma unroll
            for (int n=0;n<8;n++){
                float2 bb = *reinterpret_cast<const float2*>(&Bs[buf][wn*64 + n*8 + gq][ks + 2*tq]);
                b[n][0]=bb.x; b[n][1]=bb.y;
            }
            #pragma unroll
            for (int m=0;m<4;m++)
                #pragma unroll
                for (int n=0;n<8;n++)
                    mma_tf32(acc[m][n], a[m], b[n]);
        }
    }

    #pragma unroll
    for (int m=0;m<4;m++){
        const int r0g = bm + wm*64 + m*16 + gq;
        #pragma unroll
        for (int n=0;n<8;n++){
            const int cg = bn + wn*64 + n*8 + 2*tq;
            float v0=acc[m][n][0], v1=acc[m][n][1], v2=acc[m][n][2], v3=acc[m][n][3];
            if (bias){
                float b0, b1;
                if (bias2 && cg >= 256){ b0 = bias2[cg-256]; b1 = bias2[cg-255]; }
                else                   { b0 = bias[cg];      b1 = bias[cg+1];    }
                v0+=b0; v1+=b1; v2+=b0; v3+=b1;
            }
            if (Res){
                const float* rp0 = Res + (size_t)r0g*ldr + cg;
                const float* rp1 = Res + (size_t)(r0g+8)*ldr + cg;
                v0+=rp0[0]; v1+=rp0[1]; v2+=rp1[0]; v3+=rp1[1];
            }
            float2 w0, w1;
            if (round_out){ w0.x=tf32f(v0); w0.y=tf32f(v1); w1.x=tf32f(v2); w1.y=tf32f(v3); }
            else          { w0.x=v0; w0.y=v1; w1.x=v2; w1.y=v3; }
            *reinterpret_cast<float2*>(C + (size_t)r0g*ldc + cg)     = w0;
            *reinterpret_cast<float2*>(C + (size_t)(r0g+8)*ldc + cg) = w1;
            if (Cr){
                float2 q0, q1;
                q0.x=tf32f(v0); q0.y=tf32f(v1); q1.x=tf32f(v2); q1.y=tf32f(v3);
                *reinterpret_cast<float2*>(Cr + (size_t)r0g*ldc + cg)     = q0;
                *reinterpret_cast<float2*>(Cr + (size_t)(r0g+8)*ldc + cg) = q1;
            }
        }
    }
}

// ---------------- flash attention: P kept in registers (accumulator==a-frag) ----------------
#define QP_LD 72
#define KV_LD 72
#define FA_SMEM ((128*QP_LD + 2*64*KV_LD + 2*64*KV_LD)*4)

__global__ void __launch_bounds__(128,2)
flash_k(const float* __restrict__ Qb, const float* __restrict__ Kb,
        const float* __restrict__ Vb, float* __restrict__ Ob, int mode)
{
    extern __shared__ float smf[];
    float* QP = smf;
    float* Ks = smf + 128*QP_LD;
    float* Vs = Ks + 2*64*KV_LD;

    const int z = blockIdx.y, it = blockIdx.x;
    const int tid = threadIdx.x, warp = tid>>5, lane = tid&31;
    const int gq = lane>>2, tq = lane&3;

    size_t qoff, kvoff, ooff;
    int ld;
    if (mode == 0){
        qoff = (size_t)z*Nn*HDd; kvoff = qoff;
        ooff = (size_t)(z>>2)*Nn*Dd + (size_t)(z&3)*HDd;
        ld = HDd;
    } else {
        int h = z>>4, zz = z&15;
        size_t f = (size_t)(zz>>2)*Nn*512 + (size_t)(zz&3)*HDd;
        qoff  = (size_t)h*((size_t)Bb*Nn*512) + f;
        kvoff = (size_t)(1-h)*((size_t)Bb*Nn*512) + f;
        ooff  = (size_t)h*BND + (size_t)(zz>>2)*Nn*Dd + (size_t)(zz&3)*HDd;
        ld = 512;
    }

    const float* Q = Qb + qoff + (size_t)it*128*ld;
    const float* K = Kb + kvoff;
    const float* V = Vb + kvoff;
    float* O = Ob + ooff + (size_t)it*128*Dd;

    const int kr = tid>>4, kc = (tid&15)*4;
    auto load_kv = [&](int buf, int j0){
        #pragma unroll
        for (int itr=0; itr<8; itr++){
            int row = kr + itr*8;
            cpa16(smem_u32(Ks + ((size_t)buf*64 + row)*KV_LD + kc), K + (size_t)(j0+row)*ld + kc);
        }
        #pragma unroll
        for (int itr=0; itr<8; itr++){
            int row = kr + itr*8;
            cpa16(smem_u32(Vs + ((size_t)buf*64 + row)*KV_LD + kc), V + (size_t)(j0+row)*ld + kc);
        }
        cpa_commit();
    };

    load_kv(0, 0);

    // stage Q (pre-rounded; *0.125 exact)
    #pragma unroll
    for (int r=0;r<16;r++){
        int idx = tid + r*128;
        int row = idx>>4, c4 = idx&15;
        float4 qv = *reinterpret_cast<const float4*>(Q + (size_t)row*ld + c4*4);
        QP[row*QP_LD + c4*4+0] = qv.x*0.125f;
        QP[row*QP_LD + c4*4+1] = qv.y*0.125f;
        QP[row*QP_LD + c4*4+2] = qv.z*0.125f;
        QP[row*QP_LD + c4*4+3] = qv.w*0.125f;
    }
    __syncthreads();

    // Q a-fragments, k-lane remap: lane tq -> col 2tq, lane tq+4 -> col 2tq+1
    const int r0 = warp*32 + gq;
    float aq[2][8][4];
    #pragma unroll
    for (int g=0; g<2; g++){
        int rg = r0 + g*16;
        #pragma unroll
        for (int kk=0;kk<8;kk++){
            float2 q02 = *reinterpret_cast<const float2*>(&QP[ rg    *QP_LD + kk*8 + 2*tq]);
            float2 q13 = *reinterpret_cast<const float2*>(&QP[(rg+8)*QP_LD + kk*8 + 2*tq]);
            aq[g][kk][0]=q02.x; aq[g][kk][2]=q02.y;
            aq[g][kk][1]=q13.x; aq[g][kk][3]=q13.y;
        }
    }

    float o[2][8][4];
    #pragma unroll
    for (int g=0;g<2;g++)
        #pragma unroll
        for (int i=0;i<8;i++){ o[g][i][0]=0.f;o[g][i][1]=0.f;o[g][i][2]=0.f;o[g][i][3]=0.f; }
    float mrow[4] = {-1e30f,-1e30f,-1e30f,-1e30f};
    float lrow[4] = {0.f,0.f,0.f,0.f};

    const int NT = Nn/64;
    for (int j=0;j<NT;j++){
        const int buf = j&1;
        cpa_wait<0>();
        __syncthreads();    // also orders compute(j-1) before prefetch below overwrites
        if (j+1 < NT) load_kv(buf^1, (j+1)*64);

        const float* Kb_ = Ks + (size_t)buf*64*KV_LD;
        const float* Vb_ = Vs + (size_t)buf*64*KV_LD;

        // S = (Q*scale) K^T ; K b-frags LDS.64 via remap
        float c[2][8][4];
        #pragma unroll
        for (int nf=0;nf<8;nf++){
            #pragma unroll
            for (int g=0;g<2;g++){ c[g][nf][0]=0.f;c[g][nf][1]=0.f;c[g][nf][2]=0.f;c[g][nf][3]=0.f; }
            #pragma unroll
            for (int kk=0;kk<8;kk++){
                float2 bb = *reinterpret_cast<const float2*>(&Kb_[(nf*8+gq)*KV_LD + kk*8 + 2*tq]);
                float b[2] = {bb.x, bb.y};
                mma_tf32(c[0][nf], aq[0][kk], b);
                mma_tf32(c[1][nf], aq[1][kk], b);
            }
        }

        // online softmax; P stays in c registers
        #pragma unroll
        for (int g=0;g<2;g++){
            float mx0=-1e30f, mx1=-1e30f;
            #pragma unroll
            for (int nf=0;nf<8;nf++){
                mx0 = fmaxf(mx0, fmaxf(c[g][nf][0], c[g][nf][1]));
                mx1 = fmaxf(mx1, fmaxf(c[g][nf][2], c[g][nf][3]));
            }
            mx0 = fmaxf(mx0, __shfl_xor_sync(0xffffffffu, mx0, 1));
            mx0 = fmaxf(mx0, __shfl_xor_sync(0xffffffffu, mx0, 2));
            mx1 = fmaxf(mx1, __shfl_xor_sync(0xffffffffu, mx1, 1));
            mx1 = fmaxf(mx1, __shfl_xor_sync(0xffffffffu, mx1, 2));
            float nm0 = fmaxf(mrow[g*2],   mx0);
            float nm1 = fmaxf(mrow[g*2+1], mx1);
            float al0 = __expf(mrow[g*2]  -nm0);
            float al1 = __expf(mrow[g*2+1]-nm1);
            float s0=0.f, s1=0.f;
            #pragma unroll
            for (int nf=0;nf<8;nf++){
                c[g][nf][0]=__expf(c[g][nf][0]-nm0); c[g][nf][1]=__expf(c[g][nf][1]-nm0);
                c[g][nf][2]=__expf(c[g][nf][2]-nm1); c[g][nf][3]=__expf(c[g][nf][3]-nm1);
                s0 += c[g][nf][0]+c[g][nf][1]; s1 += c[g][nf][2]+c[g][nf][3];
            }
            s0 += __shfl_xor_sync(0xffffffffu, s0, 1);
            s0 += __shfl_xor_sync(0xffffffffu, s0, 2);
            s1 += __shfl_xor_sync(0xffffffffu, s1, 1);
            s1 += __shfl_xor_sync(0xffffffffu, s1, 2);
            lrow[g*2]   = lrow[g*2]*al0   + s0;
            lrow[g*2+1] = lrow[g*2+1]*al1 + s1;
            mrow[g*2] = nm0; mrow[g*2+1] = nm1;
            #pragma unroll
            for (int nd=0;nd<8;nd++){
                o[g][nd][0]*=al0; o[g][nd][1]*=al0; o[g][nd][2]*=al1; o[g][nd][3]*=al1;
            }
        }

        // O += P V : P a-frag = accumulator permutation {c0,c2,c1,c3} (k-lane remap)
        #pragma unroll
        for (int kk=0;kk<8;kk++){
            float ap0[4] = { c[0][kk][0], c[0][kk][2], c[0][kk][1], c[0][kk][3] };
            float ap1[4] = { c[1][kk][0], c[1][kk][2], c[1][kk][1], c[1][kk][3] };
            #pragma unroll
            for (int nd=0;nd<8;nd++){
                float b[2];
                b[0] = Vb_[(kk*8+2*tq  )*KV_LD + nd*8 + gq];
                b[1] = Vb_[(kk*8+2*tq+1)*KV_LD + nd*8 + gq];
                mma_tf32(o[0][nd], ap0, b);
                mma_tf32(o[1][nd], ap1, b);
            }
        }
    }

    #pragma unroll
    for (int g=0;g<2;g++){
        int rg = r0 + g*16;
        const float inv0 = 1.f/lrow[g*2], inv1 = 1.f/lrow[g*2+1];
        #pragma unroll
        for (int nd=0;nd<8;nd++){
            float2 w0; w0.x = tf32f(o[g][nd][0]*inv0); w0.y = tf32f(o[g][nd][1]*inv0);
            float2 w1; w1.x = tf32f(o[g][nd][2]*inv1); w1.y = tf32f(o[g][nd][3]*inv1);
            *reinterpret_cast<float2*>(O + (size_t) rg   *Dd + nd*8 + 2*tq) = w0;
            *reinterpret_cast<float2*>(O + (size_t)(rg+8)*Dd + nd*8 + 2*tq) = w1;
        }
    }
}

// ---------------- prep: weights round + init x/xr (one launch) ----------------
__global__ void prep_k(const float* a,const float* b,const float* c,const float* d,
                       const float* e,const float* f,const float* g,const float* h,
                       const float* i, const float* d0, const float* d1)
{
    int t = blockIdx.x*blockDim.x + threadIdx.x;
    switch (blockIdx.y){
        case 0: if (t<196608) w_qkv[t]        = tf32f(a[t]); break;
        case 1: if (t<65536)  w_out[t]        = tf32f(b[t]); break;
        case 2: if (t<262144) w_s1[t]         = tf32f(c[t]); break;
        case 3: if (t<131072) w_s2[t]         = tf32f(d[t]); break;
        case 4: if (t<65536)  w_cqkv[t]       = tf32f(e[t]); break;
        case 5: if (t<65536)  w_cqkv[65536+t] = tf32f(f[t]); break;
        case 6: if (t<65536)  w_co[t]         = tf32f(g[t]); break;
        case 7: if (t<262144) w_c1[t]         = tf32f(h[t]); break;
        case 8: if (t<131072) w_c2[t]         = tf32f(i[t]); break;
        case 9:
            if (t < 2*(int)BND){
                float v = (t < (int)BND) ? d0[t] : d1[t-(int)BND];
                g_x[t] = v; g_xr[t] = tf32f(v);
            }
            break;
    }
}

__global__ void qkv_rope_k(const float* __restrict__ qkv,
                           const float* __restrict__ enc0,
                           const float* __restrict__ enc1,
                           float* __restrict__ Q, float* __restrict__ K,
                           float* __restrict__ V)
{
    int idx = blockIdx.x*blockDim.x + threadIdx.x;
    const int total = 2*Bb*Hh*Nn*(HDd/2);
    if (idx >= total) return;
    int p = idx % (HDd/2); int t = idx / (HDd/2);
    int n = t % Nn; t /= Nn;
    int h = t % Hh; t /= Hh;
    int b = t % Bb; int s = t / Bb;
    size_t r = (size_t)(s*Bb + b)*Nn + n;
    const float* row = qkv + r*(3*Dd);
    int d0 = 2*p, d1 = 2*p+1;
    float q0 = row[h*192 + d0*3 + 0], q1 = row[h*192 + d1*3 + 0];
    float k0 = row[h*192 + d0*3 + 1], k1 = row[h*192 + d1*3 + 1];
    float v0 = row[h*192 + d0*3 + 2], v1 = row[h*192 + d1*3 + 2];
    const float* enc = s ? enc1 : enc0;
    size_t eoff = ((size_t)b*Nn + n)*HDd;
    float c = enc[eoff + d0];
    float si = enc[(size_t)Bb*Nn*HDd + eoff + d0];
    float qo0 = q0*c - q1*si, qo1 = q1*c + q0*si;
    float ko0 = k0*c - k1*si, ko1 = k1*c + k0*si;
    size_t bh = (size_t)(s*Bb + b)*Hh + h;
    size_t o = (bh*Nn + n)*HDd;
    Q[o+d0]=tf32f(qo0); Q[o+d1]=tf32f(qo1);
    K[o+d0]=tf32f(ko0); K[o+d1]=tf32f(ko1);
    V[o+d0]=tf32f(v0);  V[o+d1]=tf32f(v1);
}

__global__ void ln_gelu_k(float* __restrict__ X, const float* __restrict__ g,
                          const float* __restrict__ be)
{
    float* p = X + (size_t)blockIdx.x * 512;
    int tid = threadIdx.x;
    float a = p[tid], b = p[tid+256];
    float s = a + b;
    float sq = a*a + b*b;
    #pragma unroll
    for (int o=16;o;o>>=1){ s += __shfl_xor_sync(0xffffffffu,s,o);
                            sq += __shfl_xor_sync(0xffffffffu,sq,o); }
    __shared__ float ss[8], sqs[8];
    if ((tid&31)==0){ ss[tid>>5]=s; sqs[tid>>5]=sq; }
    __syncthreads();
    s = 0.f; sq = 0.f;
    #pragma unroll
    for (int t=0;t<8;t++){ s+=ss[t]; sq+=sqs[t]; }
    float mean = s * (1.0f/512.0f);
    float var  = sq * (1.0f/512.0f) - mean*mean;
    float inv = rsqrtf(var + 1e-5f);
    float y0 = (a-mean)*inv*g[tid]     + be[tid];
    float y1 = (b-mean)*inv*g[tid+256] + be[tid+256];
    p[tid]     = tf32f(0.5f*y0*(1.0f+erff(y0*0.70710678118f)));
    p[tid+256] = tf32f(0.5f*y1*(1.0f+erff(y1*0.70710678118f)));
}

// ================= host orchestration =================
extern "C" void kernel_launch(void* const* d_in, const int* in_sizes, int n_in,
                              void* d_out, int out_size)
{
    const float* desc0  = (const float*)d_in[0];
    const float* desc1  = (const float*)d_in[1];
    const float* enc0   = (const float*)d_in[2];
    const float* enc1   = (const float*)d_in[3];
    const float* s_Wqkv = (const float*)d_in[4];
    const float* s_bqkv = (const float*)d_in[5];
    const float* s_Wout = (const float*)d_in[6];
    const float* s_bout = (const float*)d_in[7];
    const float* s_W1   = (const float*)d_in[8];
    const float* s_b1   = (const float*)d_in[9];
    const float* s_g    = (const float*)d_in[10];
    const float* s_be   = (const float*)d_in[11];
    const float* s_W2   = (const float*)d_in[12];
    const float* s_b2   = (const float*)d_in[13];
    const float* c_Wqk  = (const float*)d_in[14];
    const float* c_bqk  = (const float*)d_in[15];
    const float* c_Wv   = (const float*)d_in[16];
    const float* c_bv   = (const float*)d_in[17];
    const float* c_Wo   = (const float*)d_in[18];
    const float* c_bo   = (const float*)d_in[19];
    const float* c_W1   = (const float*)d_in[20];
    const float* c_b1   = (const float*)d_in[21];
    const float* c_g    = (const float*)d_in[22];
    const float* c_be   = (const float*)d_in[23];
    const float* c_W2   = (const float*)d_in[24];
    const float* c_b2   = (const float*)d_in[25];
    float* out = (float*)d_out;

    float *x,*xr,*qkv,*q,*k,*v,*tmp,*hb;
    float *wqkv,*wout,*ws1,*ws2,*wcqkv,*wco,*wc1,*wc2;
    cudaGetSymbolAddress((void**)&x,   g_x);
    cudaGetSymbolAddress((void**)&xr,  g_xr);
    cudaGetSymbolAddress((void**)&qkv, g_qkv);
    cudaGetSymbolAddress((void**)&q,   g_q);
    cudaGetSymbolAddress((void**)&k,   g_k);
    cudaGetSymbolAddress((void**)&v,   g_v);
    cudaGetSymbolAddress((void**)&tmp, g_tmp);
    cudaGetSymbolAddress((void**)&hb,  g_h);
    cudaGetSymbolAddress((void**)&wqkv, w_qkv);
    cudaGetSymbolAddress((void**)&wout, w_out);
    cudaGetSymbolAddress((void**)&ws1,  w_s1);
    cudaGetSymbolAddress((void**)&ws2,  w_s2);
    cudaGetSymbolAddress((void**)&wcqkv,w_cqkv);
    cudaGetSymbolAddress((void**)&wco,  w_co);
    cudaGetSymbolAddress((void**)&wc1,  w_c1);
    cudaGetSymbolAddress((void**)&wc2,  w_c2);

    cudaFuncSetAttribute(flash_k, cudaFuncAttributeMaxDynamicSharedMemorySize, FA_SMEM);
    cudaFuncSetAttribute(mgemm,   cudaFuncAttributeMaxDynamicSharedMemorySize, MG_SMEM);

    auto GE = [&](const float* A,const float* A2,int lda,const float* W,int ldb,
                  float* C,int ldc,const float* bias,const float* bias2,
                  const float* Res,int ldr,int M,int Nc,int K,int ro,float* Cr){
        dim3 gr(Nc/128, M/128);
        mgemm<<<gr,128,MG_SMEM>>>(A,A2,lda,W,ldb,C,ldc,bias,bias2,Res,ldr,K,ro,Cr);
    };

    // 1: prep
    {
        dim3 gr((2*(int)BND+255)/256, 10);
        prep_k<<<gr,256>>>(s_Wqkv,s_Wout,s_W1,s_W2,c_Wqk,c_Wv,c_Wo,c_W1,c_W2,desc0,desc1);
    }
    // 2: qkv
    GE(xr,nullptr,Dd, wqkv,Dd, qkv,3*Dd, s_bqkv,nullptr, nullptr,0, M2,3*Dd,Dd, 0,nullptr);
    // 3: rope
    {
        int total = 2*Bb*Hh*Nn*(HDd/2);
        qkv_rope_k<<<(total+255)/256,256>>>(qkv, enc0, enc1, q, k, v);
    }
    // 4: flash self -> tmp   [ncu window]
    {
        dim3 gr(Nn/128, 2*Bb*Hh);
        flash_k<<<gr,128,FA_SMEM>>>(q, k, v, tmp, 0);
    }
    // 5: msg
    GE(tmp,nullptr,Dd, wout,Dd, qkv,Dd, s_bout,nullptr, nullptr,0, M2,Dd,Dd, 1,nullptr);
    GE(xr,qkv,Dd, ws1,2*Dd, hb,2*Dd, s_b1,nullptr, nullptr,0, M2,2*Dd,2*Dd, 0,nullptr);
    ln_gelu_k<<<M2,256>>>(hb, s_g, s_be);
    GE(hb,nullptr,2*Dd, ws2,2*Dd, x,Dd, s_b2,nullptr, x,Dd, M2,Dd,2*Dd, 0,xr);

    // ======== CROSS block ========
    GE(xr,nullptr,Dd, wcqkv,Dd, hb,512, c_bqk,c_bv, nullptr,0, M2,512,Dd, 1,nullptr);
    {
        dim3 gr(Nn/128, 2*Bb*Hh);
        flash_k<<<gr,128,FA_SMEM>>>(hb, hb, hb+256, qkv, 1);
    }
    GE(qkv,nullptr,Dd, wco,Dd, tmp,Dd, c_bo,nullptr, nullptr,0, M2,Dd,Dd, 1,nullptr);
    GE(xr,tmp,Dd, wc1,2*Dd, hb,2*Dd, c_b1,nullptr, nullptr,0, M2,2*Dd,2*Dd, 0,nullptr);
    ln_gelu_k<<<M2,256>>>(hb, c_g, c_be);
    GE(hb,nullptr,2*Dd, wc2,2*Dd, out,Dd, c_b2,nullptr, x,Dd, M2,Dd,2*Dd, 0,nullptr);
}

// round 17
// speedup vs baseline: 1.2251x; 1.2251x over previous
#include <cuda_runtime.h>
#include <cuda_fp16.h>
#include <math.h>
#include <stdint.h>

#define Bb 4
#define Nn 2048
#define Dd 256
#define Hh 4
#define HDd 64
#define M2 (2*Bb*Nn)
#define BND ((size_t)Bb*Nn*Dd)
#define SQS 0.35355339059327373f

// ---------------- static scratch ----------------
__device__ float g_x  [(size_t)M2*Dd];
__device__ float g_xr [(size_t)M2*Dd];
__device__ float g_qkv[(size_t)M2*3*Dd];
__device__ float g_q  [(size_t)2*Bb*Hh*Nn*HDd];   // fp16 qh lives here
__device__ float g_k  [(size_t)2*Bb*Hh*Nn*HDd];   // fp16 kh
__device__ float g_v  [(size_t)2*Bb*Hh*Nn*HDd];   // fp16 vph (interleaved)
__device__ float g_tmp[(size_t)M2*Dd];
__device__ float g_h  [(size_t)M2*2*Dd];          // hb; cross: aliased as h_qk/h_vp halves
// pre-rounded weights (tf32)
__device__ float w_qkv [768*256];
__device__ float w_out [256*256];
__device__ float w_s1  [512*512];
__device__ float w_s2  [256*512];
__device__ float w_cqkv[512*256];
__device__ float w_co  [256*256];
__device__ float w_c1  [512*512];
__device__ float w_c2  [256*512];

__device__ __forceinline__ float tf32f(float x){
    float y; asm("cvt.rna.tf32.f32 %0, %1;" : "=f"(y) : "f"(x)); return y;
}

// ---------------- cp.async helpers ----------------
__device__ __forceinline__ void cpa16(uint32_t s, const void* g){
    asm volatile("cp.async.cg.shared.global [%0], [%1], 16;\n" :: "r"(s), "l"(g));
}
__device__ __forceinline__ void cpa_commit(){ asm volatile("cp.async.commit_group;\n"); }
template<int N> __device__ __forceinline__ void cpa_wait(){
    asm volatile("cp.async.wait_group %0;\n" :: "n"(N));
}
__device__ __forceinline__ uint32_t smem_u32(const void* p){
    uint32_t a;
    asm("{ .reg .u64 t; cvta.to.shared.u64 t, %1; cvt.u32.u64 %0, t; }" : "=r"(a) : "l"(p));
    return a;
}

// ---------------- mma.sync wrappers ----------------
__device__ __forceinline__ void mma_tf32(float* c, const float* a, const float* b){
    asm volatile(
      "mma.sync.aligned.m16n8k8.row.col.f32.tf32.tf32.f32 "
      "{%0,%1,%2,%3},{%4,%5,%6,%7},{%8,%9},{%0,%1,%2,%3};\n"
      : "+f"(c[0]),"+f"(c[1]),"+f"(c[2]),"+f"(c[3])
      : "r"(__float_as_uint(a[0])),"r"(__float_as_uint(a[1])),
        "r"(__float_as_uint(a[2])),"r"(__float_as_uint(a[3])),
        "r"(__float_as_uint(b[0])),"r"(__float_as_uint(b[1])));
}
__device__ __forceinline__ void mma_f16(float* c, const uint32_t* a, uint32_t b0, uint32_t b1){
    asm volatile(
      "mma.sync.aligned.m16n8k16.row.col.f32.f16.f16.f32 "
      "{%0,%1,%2,%3},{%4,%5,%6,%7},{%8,%9},{%0,%1,%2,%3};\n"
      : "+f"(c[0]),"+f"(c[1]),"+f"(c[2]),"+f"(c[3])
      : "r"(a[0]),"r"(a[1]),"r"(a[2]),"r"(a[3]),"r"(b0),"r"(b1));
}
__device__ __forceinline__ uint32_t h2u(__half2 h){
    uint32_t u; *reinterpret_cast<__half2*>(&u) = h; return u;
}

// ---------------- NT tf32 GEMM (core unchanged; +cross_out fp16 epilogue) ----------------
#define GLD 24
#define MG_SMEM (3*128*GLD*2*4)
__global__ void __launch_bounds__(128,2)
mgemm(const float* __restrict__ A, const float* __restrict__ A2, int lda,
      const float* __restrict__ W, int ldb,
      float* __restrict__ C, int ldc,
      const float* __restrict__ bias, const float* __restrict__ bias2,
      const float* __restrict__ Res, int ldr,
      int K, int round_out, float* __restrict__ Cr,
      int cross_out, __half* __restrict__ Hq, __half* __restrict__ Hv)
{
    extern __shared__ float dsm[];
    float (*As)[128][GLD] = reinterpret_cast<float(*)[128][GLD]>(dsm);
    float (*Bs)[128][GLD] = reinterpret_cast<float(*)[128][GLD]>(dsm + 3*128*GLD);

    const int bm = blockIdx.y*128, bn = blockIdx.x*128;
    const int tid = threadIdx.x, warp = tid>>5, lane = tid&31;
    const int wm = warp>>1, wn = warp&1;
    const int gq = lane>>2, tq = lane&3;

    float acc[4][8][4];
    #pragma unroll
    for (int m=0;m<4;m++)
        #pragma unroll
        for (int n=0;n<8;n++){
            acc[m][n][0]=0.f; acc[m][n][1]=0.f; acc[m][n][2]=0.f; acc[m][n][3]=0.f;
        }

    auto ld_tile = [&](int st, int k0){
        const float* Ab; int ka;
        if (A2 && k0 >= 256){ Ab = A2; ka = k0 - 256; } else { Ab = A; ka = k0; }
        #pragma unroll
        for (int i=0;i<4;i++){
            int id = tid + i*128;
            int row = id>>2, c4 = id&3;
            cpa16(smem_u32(&As[st][row][c4*4]), Ab + (size_t)(bm+row)*((A2)?256:lda) + ka + c4*4);
        }
        #pragma unroll
        for (int i=0;i<4;i++){
            int id = tid + i*128;
            int row = id>>2, c4 = id&3;
            cpa16(smem_u32(&Bs[st][row][c4*4]), W + (size_t)(bn+row)*ldb + k0 + c4*4);
        }
        cpa_commit();
    };

    const int KT = K/16;
    ld_tile(0, 0);
    ld_tile(1, 16);

    for (int kt=0; kt<KT; kt++){
        const int buf = kt%3;
        if (kt+1 < KT) cpa_wait<1>(); else cpa_wait<0>();
        __syncthreads();
        if (kt+2 < KT) ld_tile((kt+2)%3, (kt+2)*16);
        #pragma unroll
        for (int ks=0; ks<16; ks+=8){
            float a[4][4], b[8][2];
            #pragma unroll
            for (int m=0;m<4;m++){
                float2 a02 = *reinterpret_cast<const float2*>(&As[buf][wm*64 + m*16 + gq    ][ks + 2*tq]);
                float2 a13 = *reinterpret_cast<const float2*>(&As[buf][wm*64 + m*16 + gq + 8][ks + 2*tq]);
                a[m][0]=a02.x; a[m][2]=a02.y; a[m][1]=a13.x; a[m][3]=a13.y;
            }
            #pragma unroll
            for (int n=0;n<8;n++){
                float2 bb = *reinterpret_cast<const float2*>(&Bs[buf][wn*64 + n*8 + gq][ks + 2*tq]);
                b[n][0]=bb.x; b[n][1]=bb.y;
            }
            #pragma unroll
            for (int m=0;m<4;m++)
                #pragma unroll
                for (int n=0;n<8;n++)
                    mma_tf32(acc[m][n], a[m], b[n]);
        }
    }

    #pragma unroll
    for (int m=0;m<4;m++){
        const int r0g = bm + wm*64 + m*16 + gq;
        #pragma unroll
        for (int n=0;n<8;n++){
            const int cg = bn + wn*64 + n*8 + 2*tq;
            float v0=acc[m][n][0], v1=acc[m][n][1], v2=acc[m][n][2], v3=acc[m][n][3];
            if (bias){
                float b0, b1;
                if (bias2 && cg >= 256){ b0 = bias2[cg-256]; b1 = bias2[cg-255]; }
                else                   { b0 = bias[cg];      b1 = bias[cg+1];    }
                v0+=b0; v1+=b1; v2+=b0; v3+=b1;
            }
            if (Res){
                const float* rp0 = Res + (size_t)r0g*ldr + cg;
                const float* rp1 = Res + (size_t)(r0g+8)*ldr + cg;
                v0+=rp0[0]; v1+=rp0[1]; v2+=rp1[0]; v3+=rp1[1];
            }
            if (cross_out){
                // cols<256: qk half, scaled by sqrt(0.125). cols>=256: v half, pair-interleaved.
                if (cg < 256){
                    __half2 h0 = __floats2half2_rn(v0*SQS, v1*SQS);
                    __half2 h1 = __floats2half2_rn(v2*SQS, v3*SQS);
                    *reinterpret_cast<__half2*>(Hq + (size_t)r0g*256 + cg)     = h0;
                    *reinterpret_cast<__half2*>(Hq + (size_t)(r0g+8)*256 + cg) = h1;
                } else {
                    int cc = cg - 256;
                    size_t a0 = ((size_t)(r0g>>1))*512 + (size_t)cc*2 + (r0g&1);
                    size_t a1 = ((size_t)((r0g+8)>>1))*512 + (size_t)cc*2 + ((r0g+8)&1);
                    Hv[a0]   = __float2half(v0);
                    Hv[a0+2] = __float2half(v1);
                    Hv[a1]   = __float2half(v2);
                    Hv[a1+2] = __float2half(v3);
                }
                continue;
            }
            float2 w0, w1;
            if (round_out){ w0.x=tf32f(v0); w0.y=tf32f(v1); w1.x=tf32f(v2); w1.y=tf32f(v3); }
            else          { w0.x=v0; w0.y=v1; w1.x=v2; w1.y=v3; }
            *reinterpret_cast<float2*>(C + (size_t)r0g*ldc + cg)     = w0;
            *reinterpret_cast<float2*>(C + (size_t)(r0g+8)*ldc + cg) = w1;
            if (Cr){
                float2 q0, q1;
                q0.x=tf32f(v0); q0.y=tf32f(v1); q1.x=tf32f(v2); q1.y=tf32f(v3);
                *reinterpret_cast<float2*>(Cr + (size_t)r0g*ldc + cg)     = q0;
                *reinterpret_cast<float2*>(Cr + (size_t)(r0g+8)*ldc + cg) = q1;
            }
        }
    }
}

// ---------------- fp16 flash attention: 4 warps x 32 q-rows ----------------
// Q pre-scaled at producer. Q/K fp16 row-major; V fp16 pair-interleaved Vp[j/2][d][j&1].
// S-phase uses 4tq k-remap (LDS.64 frags); PV uses natural pairing, P packed to half2.
#define QH_LD 80   // halves
#define KH_LD 80   // halves
#define VP_LD 72   // half2 units
#define FA_SMEM ((128*QH_LD + 2*64*KH_LD)*2 + 2*32*VP_LD*4)   // 59392 B

__global__ void __launch_bounds__(128,2)
flash_k(const __half* __restrict__ Qb, const __half* __restrict__ Kb,
        const __half* __restrict__ Vb, float* __restrict__ Ob, int mode)
{
    extern __shared__ char smc[];
    __half* Qs = reinterpret_cast<__half*>(smc);            // [128][QH_LD]
    __half* Ks = Qs + 128*QH_LD;                            // [2][64][KH_LD]
    uint32_t* Vs = reinterpret_cast<uint32_t*>(Ks + 2*64*KH_LD); // half2 [2][32][VP_LD]

    const int z = blockIdx.y, it = blockIdx.x;
    const int tid = threadIdx.x, warp = tid>>5, lane = tid&31;
    const int gq = lane>>2, tq = lane&3;

    size_t qoff, koff, voff, ooff;
    int qld, kld, vld;
    if (mode == 0){
        qoff = (size_t)z*Nn*HDd; koff = qoff;
        voff = (size_t)z*(Nn/2)*128;
        ooff = (size_t)(z>>2)*Nn*Dd + (size_t)(z&3)*HDd;
        qld = HDd; kld = HDd; vld = 128;
    } else {
        int h = z>>4, zz = z&15, b = zz>>2, hh = zz&3;
        qoff = ((size_t)(h*Bb+b)*Nn)*256 + (size_t)hh*64;
        koff = ((size_t)((1-h)*Bb+b)*Nn)*256 + (size_t)hh*64;
        voff = ((size_t)((1-h)*Bb+b)*(Nn/2))*512 + (size_t)hh*128;
        ooff = (size_t)h*BND + (size_t)b*Nn*Dd + (size_t)hh*64;
        qld = 256; kld = 256; vld = 512;
    }

    const __half* Q = Qb + qoff + (size_t)it*128*qld;
    const __half* K = Kb + koff;
    const __half* Vg = Vb + voff;
    float* O = Ob + ooff + (size_t)it*128*Dd;

    // loaders
    const int krow = tid>>3, kch = tid&7;      // K: 64 rows x 8x16B
    const int vrow = tid>>4, vch = tid&15;     // V: 32 rows x 16x16B
    auto load_kv = [&](int buf, int j0){
        #pragma unroll
        for (int itr=0; itr<4; itr++){
            int row = krow + itr*16;
            cpa16(smem_u32(Ks + ((size_t)buf*64 + row)*KH_LD + kch*8),
                  K + (size_t)(j0+row)*kld + kch*8);
        }
        #pragma unroll
        for (int itr=0; itr<4; itr++){
            int row = vrow + itr*8;
            cpa16(smem_u32(Vs + ((size_t)buf*32 + row)*VP_LD + vch*4),
                  Vg + (size_t)((j0>>1)+row)*vld + vch*8);
        }
        cpa_commit();
    };

    load_kv(0, 0);
    // stage Q via cp.async (fp16, pre-scaled at producer)
    {
        int qrow = tid>>3, qch = tid&7;
        #pragma unroll
        for (int itr=0; itr<8; itr++){
            int row = qrow + itr*16;
            cpa16(smem_u32(Qs + (size_t)row*QH_LD + qch*8), Q + (size_t)row*qld + qch*8);
        }
        cpa_commit();
    }
    cpa_wait<0>();
    __syncthreads();

    // Q a-fragments: 4tq k-remap, LDS.64 pairs
    const int r0 = warp*32 + gq;
    uint32_t aq[2][4][4];
    #pragma unroll
    for (int g=0; g<2; g++){
        int rg = r0 + g*16;
        #pragma unroll
        for (int kb=0; kb<4; kb++){
            uint2 lo = *reinterpret_cast<const uint2*>(&Qs[(size_t)rg    *QH_LD + kb*16 + 4*tq]);
            uint2 hi = *reinterpret_cast<const uint2*>(&Qs[(size_t)(rg+8)*QH_LD + kb*16 + 4*tq]);
            aq[g][kb][0]=lo.x; aq[g][kb][2]=lo.y; aq[g][kb][1]=hi.x; aq[g][kb][3]=hi.y;
        }
    }

    float o[2][8][4];
    #pragma unroll
    for (int g=0;g<2;g++)
        #pragma unroll
        for (int i=0;i<8;i++){ o[g][i][0]=0.f;o[g][i][1]=0.f;o[g][i][2]=0.f;o[g][i][3]=0.f; }
    float mrow[4] = {-1e30f,-1e30f,-1e30f,-1e30f};
    float lrow[4] = {0.f,0.f,0.f,0.f};

    const int NT = Nn/64;
    for (int j=0;j<NT;j++){
        const int buf = j&1;
        cpa_wait<0>();
        __syncthreads();
        if (j+1 < NT) load_kv(buf^1, (j+1)*64);

        const __half* Kb_ = Ks + (size_t)buf*64*KH_LD;
        const uint32_t* Vb_ = Vs + (size_t)buf*32*VP_LD;

        // S = Q K^T (fp16 mma, k16)
        float c[2][8][4];
        #pragma unroll
        for (int nf=0;nf<8;nf++){
            #pragma unroll
            for (int g=0;g<2;g++){ c[g][nf][0]=0.f;c[g][nf][1]=0.f;c[g][nf][2]=0.f;c[g][nf][3]=0.f; }
            #pragma unroll
            for (int kb=0;kb<4;kb++){
                uint2 bb = *reinterpret_cast<const uint2*>(&Kb_[(size_t)(nf*8+gq)*KH_LD + kb*16 + 4*tq]);
                mma_f16(c[0][nf], aq[0][kb], bb.x, bb.y);
                mma_f16(c[1][nf], aq[1][kb], bb.x, bb.y);
            }
        }

        // online softmax; P packed to half2 (fp32 exp)
        uint32_t ph0[2][8], ph1[2][8];
        #pragma unroll
        for (int g=0;g<2;g++){
            float mx0=-1e30f, mx1=-1e30f;
            #pragma unroll
            for (int nf=0;nf<8;nf++){
                mx0 = fmaxf(mx0, fmaxf(c[g][nf][0], c[g][nf][1]));
                mx1 = fmaxf(mx1, fmaxf(c[g][nf][2], c[g][nf][3]));
            }
            mx0 = fmaxf(mx0, __shfl_xor_sync(0xffffffffu, mx0, 1));
            mx0 = fmaxf(mx0, __shfl_xor_sync(0xffffffffu, mx0, 2));
            mx1 = fmaxf(mx1, __shfl_xor_sync(0xffffffffu, mx1, 1));
            mx1 = fmaxf(mx1, __shfl_xor_sync(0xffffffffu, mx1, 2));
            float nm0 = fmaxf(mrow[g*2],   mx0);
            float nm1 = fmaxf(mrow[g*2+1], mx1);
            float al0 = __expf(mrow[g*2]  -nm0);
            float al1 = __expf(mrow[g*2+1]-nm1);
            float s0=0.f, s1=0.f;
            #pragma unroll
            for (int nf=0;nf<8;nf++){
                float e0=__expf(c[g][nf][0]-nm0), e1=__expf(c[g][nf][1]-nm0);
                float e2=__expf(c[g][nf][2]-nm1), e3=__expf(c[g][nf][3]-nm1);
                s0 += e0+e1; s1 += e2+e3;
                ph0[g][nf] = h2u(__floats2half2_rn(e0,e1));
                ph1[g][nf] = h2u(__floats2half2_rn(e2,e3));
            }
            s0 += __shfl_xor_sync(0xffffffffu, s0, 1);
            s0 += __shfl_xor_sync(0xffffffffu, s0, 2);
            s1 += __shfl_xor_sync(0xffffffffu, s1, 1);
            s1 += __shfl_xor_sync(0xffffffffu, s1, 2);
            lrow[g*2]   = lrow[g*2]*al0   + s0;
            lrow[g*2+1] = lrow[g*2+1]*al1 + s1;
            mrow[g*2] = nm0; mrow[g*2+1] = nm1;
            #pragma unroll
            for (int nd=0;nd<8;nd++){
                o[g][nd][0]*=al0; o[g][nd][1]*=al0; o[g][nd][2]*=al1; o[g][nd][3]*=al1;
            }
        }

        // O += P V (fp16 mma, k16); V b-frags = half2 LDS.32 from interleaved Vp
        #pragma unroll
        for (int kb=0;kb<4;kb++){
            uint32_t ap0[4] = { ph0[0][2*kb], ph1[0][2*kb], ph0[0][2*kb+1], ph1[0][2*kb+1] };
            uint32_t ap1[4] = { ph0[1][2*kb], ph1[1][2*kb], ph0[1][2*kb+1], ph1[1][2*kb+1] };
            #pragma unroll
            for (int nd=0;nd<8;nd++){
                uint32_t b0 = Vb_[(size_t)(kb*8+tq  )*VP_LD + nd*8 + gq];
                uint32_t b1 = Vb_[(size_t)(kb*8+4+tq)*VP_LD + nd*8 + gq];
                mma_f16(o[0][nd], ap0, b0, b1);
                mma_f16(o[1][nd], ap1, b0, b1);
            }
        }
    }

    #pragma unroll
    for (int g=0;g<2;g++){
        int rg = r0 + g*16;
        const float inv0 = 1.f/lrow[g*2], inv1 = 1.f/lrow[g*2+1];
        #pragma unroll
        for (int nd=0;nd<8;nd++){
            float2 w0; w0.x = tf32f(o[g][nd][0]*inv0); w0.y = tf32f(o[g][nd][1]*inv0);
            float2 w1; w1.x = tf32f(o[g][nd][2]*inv1); w1.y = tf32f(o[g][nd][3]*inv1);
            *reinterpret_cast<float2*>(O + (size_t) rg   *Dd + nd*8 + 2*tq) = w0;
            *reinterpret_cast<float2*>(O + (size_t)(rg+8)*Dd + nd*8 + 2*tq) = w1;
        }
    }
}

// ---------------- prep: weights round + init x/xr ----------------
__global__ void prep_k(const float* a,const float* b,const float* c,const float* d,
                       const float* e,const float* f,const float* g,const float* h,
                       const float* i, const float* d0, const float* d1)
{
    int t = blockIdx.x*blockDim.x + threadIdx.x;
    switch (blockIdx.y){
        case 0: if (t<196608) w_qkv[t]        = tf32f(a[t]); break;
        case 1: if (t<65536)  w_out[t]        = tf32f(b[t]); break;
        case 2: if (t<262144) w_s1[t]         = tf32f(c[t]); break;
        case 3: if (t<131072) w_s2[t]         = tf32f(d[t]); break;
        case 4: if (t<65536)  w_cqkv[t]       = tf32f(e[t]); break;
        case 5: if (t<65536)  w_cqkv[65536+t] = tf32f(f[t]); break;
        case 6: if (t<65536)  w_co[t]         = tf32f(g[t]); break;
        case 7: if (t<262144) w_c1[t]         = tf32f(h[t]); break;
        case 8: if (t<131072) w_c2[t]         = tf32f(i[t]); break;
        case 9:
            if (t < 2*(int)BND){
                float v = (t < (int)BND) ? d0[t] : d1[t-(int)BND];
                g_x[t] = v; g_xr[t] = tf32f(v);
            }
            break;
    }
}

// ---------------- rope: fp16 outputs; Q pre-scaled; V pair-interleaved ----------------
__global__ void qkv_rope_k(const float* __restrict__ qkv,
                           const float* __restrict__ enc0,
                           const float* __restrict__ enc1,
                           __half* __restrict__ Qh, __half* __restrict__ Kh,
                           __half* __restrict__ Vph)
{
    int idx = blockIdx.x*blockDim.x + threadIdx.x;
    const int total = 2*Bb*Hh*Nn*(HDd/2);
    if (idx >= total) return;
    int p = idx % (HDd/2); int t = idx / (HDd/2);
    int n = t % Nn; t /= Nn;
    int h = t % Hh; t /= Hh;
    int b = t % Bb; int s = t / Bb;
    size_t r = (size_t)(s*Bb + b)*Nn + n;
    const float* row = qkv + r*(3*Dd);
    int d0 = 2*p, d1 = 2*p+1;
    float q0 = row[h*192 + d0*3 + 0], q1 = row[h*192 + d1*3 + 0];
    float k0 = row[h*192 + d0*3 + 1], k1 = row[h*192 + d1*3 + 1];
    float v0 = row[h*192 + d0*3 + 2], v1 = row[h*192 + d1*3 + 2];
    const float* enc = s ? enc1 : enc0;
    size_t eoff = ((size_t)b*Nn + n)*HDd;
    float cc = enc[eoff + d0];
    float si = enc[(size_t)Bb*Nn*HDd + eoff + d0];
    float qo0 = q0*cc - q1*si, qo1 = q1*cc + q0*si;
    float ko0 = k0*cc - k1*si, ko1 = k1*cc + k0*si;
    size_t bh = (size_t)(s*Bb + b)*Hh + h;
    size_t oq = (bh*Nn + n)*HDd;
    *reinterpret_cast<__half2*>(Qh + oq + d0) = __floats2half2_rn(qo0*0.125f, qo1*0.125f);
    *reinterpret_cast<__half2*>(Kh + oq + d0) = __floats2half2_rn(ko0, ko1);
    size_t vb = (bh*(Nn/2) + (n>>1))*128 + (n&1);
    Vph[vb + (size_t)d0*2] = __float2half(v0);
    Vph[vb + (size_t)d1*2] = __float2half(v1);
}

__global__ void ln_gelu_k(float* __restrict__ X, const float* __restrict__ g,
                          const float* __restrict__ be)
{
    float* p = X + (size_t)blockIdx.x * 512;
    int tid = threadIdx.x;
    float a = p[tid], b = p[tid+256];
    float s = a + b;
    float sq = a*a + b*b;
    #pragma unroll
    for (int o=16;o;o>>=1){ s += __shfl_xor_sync(0xffffffffu,s,o);
                            sq += __shfl_xor_sync(0xffffffffu,sq,o); }
    __shared__ float ss[8], sqs[8];
    if ((tid&31)==0){ ss[tid>>5]=s; sqs[tid>>5]=sq; }
    __syncthreads();
    s = 0.f; sq = 0.f;
    #pragma unroll
    for (int t=0;t<8;t++){ s+=ss[t]; sq+=sqs[t]; }
    float mean = s * (1.0f/512.0f);
    float var  = sq * (1.0f/512.0f) - mean*mean;
    float inv = rsqrtf(var + 1e-5f);
    float y0 = (a-mean)*inv*g[tid]     + be[tid];
    float y1 = (b-mean)*inv*g[tid+256] + be[tid+256];
    p[tid]     = tf32f(0.5f*y0*(1.0f+erff(y0*0.70710678118f)));
    p[tid+256] = tf32f(0.5f*y1*(1.0f+erff(y1*0.70710678118f)));
}

// ================= host orchestration =================
extern "C" void kernel_launch(void* const* d_in, const int* in_sizes, int n_in,
                              void* d_out, int out_size)
{
    const float* desc0  = (const float*)d_in[0];
    const float* desc1  = (const float*)d_in[1];
    const float* enc0   = (const float*)d_in[2];
    const float* enc1   = (const float*)d_in[3];
    const float* s_Wqkv = (const float*)d_in[4];
    const float* s_bqkv = (const float*)d_in[5];
    const float* s_Wout = (const float*)d_in[6];
    const float* s_bout = (const float*)d_in[7];
    const float* s_W1   = (const float*)d_in[8];
    const float* s_b1   = (const float*)d_in[9];
    const float* s_g    = (const float*)d_in[10];
    const float* s_be   = (const float*)d_in[11];
    const float* s_W2   = (const float*)d_in[12];
    const float* s_b2   = (const float*)d_in[13];
    const float* c_Wqk  = (const float*)d_in[14];
    const float* c_bqk  = (const float*)d_in[15];
    const float* c_Wv   = (const float*)d_in[16];
    const float* c_bv   = (const float*)d_in[17];
    const float* c_Wo   = (const float*)d_in[18];
    const float* c_bo   = (const float*)d_in[19];
    const float* c_W1   = (const float*)d_in[20];
    const float* c_b1   = (const float*)d_in[21];
    const float* c_g    = (const float*)d_in[22];
    const float* c_be   = (const float*)d_in[23];
    const float* c_W2   = (const float*)d_in[24];
    const float* c_b2   = (const float*)d_in[25];
    float* out = (float*)d_out;

    float *x,*xr,*qkv,*q,*k,*v,*tmp,*hb;
    float *wqkv,*wout,*ws1,*ws2,*wcqkv,*wco,*wc1,*wc2;
    cudaGetSymbolAddress((void**)&x,   g_x);
    cudaGetSymbolAddress((void**)&xr,  g_xr);
    cudaGetSymbolAddress((void**)&qkv, g_qkv);
    cudaGetSymbolAddress((void**)&q,   g_q);
    cudaGetSymbolAddress((void**)&k,   g_k);
    cudaGetSymbolAddress((void**)&v,   g_v);
    cudaGetSymbolAddress((void**)&tmp, g_tmp);
    cudaGetSymbolAddress((void**)&hb,  g_h);
    cudaGetSymbolAddress((void**)&wqkv, w_qkv);
    cudaGetSymbolAddress((void**)&wout, w_out);
    cudaGetSymbolAddress((void**)&ws1,  w_s1);
    cudaGetSymbolAddress((void**)&ws2,  w_s2);
    cudaGetSymbolAddress((void**)&wcqkv,w_cqkv);
    cudaGetSymbolAddress((void**)&wco,  w_co);
    cudaGetSymbolAddress((void**)&wc1,  w_c1);
    cudaGetSymbolAddress((void**)&wc2,  w_c2);

    __half* qh  = (__half*)q;
    __half* kh  = (__half*)k;
    __half* vph = (__half*)v;
    __half* hqk = (__half*)hb;                       // alias: cross qk halves [M2][256]
    __half* hvp = (__half*)hb + (size_t)M2*256;      // alias: cross v interleaved

    cudaFuncSetAttribute(flash_k, cudaFuncAttributeMaxDynamicSharedMemorySize, FA_SMEM);
    cudaFuncSetAttribute(mgemm,   cudaFuncAttributeMaxDynamicSharedMemorySize, MG_SMEM);

    auto GE = [&](const float* A,const float* A2,int lda,const float* W,int ldb,
                  float* C,int ldc,const float* bias,const float* bias2,
                  const float* Res,int ldr,int M,int Nc,int K,int ro,float* Cr,
                  int cross_out, __half* Hq, __half* Hv){
        dim3 gr(Nc/128, M/128);
        mgemm<<<gr,128,MG_SMEM>>>(A,A2,lda,W,ldb,C,ldc,bias,bias2,Res,ldr,K,ro,Cr,cross_out,Hq,Hv);
    };

    // 1: prep
    {
        dim3 gr((2*(int)BND+255)/256, 10);
        prep_k<<<gr,256>>>(s_Wqkv,s_Wout,s_W1,s_W2,c_Wqk,c_Wv,c_Wo,c_W1,c_W2,desc0,desc1);
    }
    // 2: qkv
    GE(xr,nullptr,Dd, wqkv,Dd, qkv,3*Dd, s_bqkv,nullptr, nullptr,0, M2,3*Dd,Dd, 0,nullptr, 0,nullptr,nullptr);
    // 3: rope (fp16 outputs)
    {
        int total = 2*Bb*Hh*Nn*(HDd/2);
        qkv_rope_k<<<(total+255)/256,256>>>(qkv, enc0, enc1, qh, kh, vph);
    }
    // 4: flash self -> tmp   [ncu window]
    {
        dim3 gr(Nn/128, 2*Bb*Hh);
        flash_k<<<gr,128,FA_SMEM>>>(qh, kh, vph, tmp, 0);
    }
    // 5: msg
    GE(tmp,nullptr,Dd, wout,Dd, qkv,Dd, s_bout,nullptr, nullptr,0, M2,Dd,Dd, 1,nullptr, 0,nullptr,nullptr);
    GE(xr,qkv,Dd, ws1,2*Dd, hb,2*Dd, s_b1,nullptr, nullptr,0, M2,2*Dd,2*Dd, 0,nullptr, 0,nullptr,nullptr);
    ln_gelu_k<<<M2,256>>>(hb, s_g, s_be);
    GE(hb,nullptr,2*Dd, ws2,2*Dd, x,Dd, s_b2,nullptr, x,Dd, M2,Dd,2*Dd, 0,xr, 0,nullptr,nullptr);

    // ======== CROSS block ========
    // merged qk|v projection -> fp16 buffers (qk scaled by sqrt(0.125); v interleaved)
    GE(xr,nullptr,Dd, wcqkv,Dd, nullptr,512, c_bqk,c_bv, nullptr,0, M2,512,Dd, 0,nullptr, 1,hqk,hvp);
    {
        dim3 gr(Nn/128, 2*Bb*Hh);
        flash_k<<<gr,128,FA_SMEM>>>(hqk, hqk, hvp, qkv, 1);   // ctx -> qkv (tf32 fp32)
    }
    GE(qkv,nullptr,Dd, wco,Dd, tmp,Dd, c_bo,nullptr, nullptr,0, M2,Dd,Dd, 1,nullptr, 0,nullptr,nullptr);
    GE(xr,tmp,Dd, wc1,2*Dd, hb,2*Dd, c_b1,nullptr, nullptr,0, M2,2*Dd,2*Dd, 0,nullptr, 0,nullptr,nullptr);
    ln_gelu_k<<<M2,256>>>(hb, c_g, c_be);
    GE(hb,nullptr,2*Dd, wc2,2*Dd, out,Dd, c_b2,nullptr, x,Dd, M2,Dd,2*Dd, 0,nullptr, 0,nullptr,nullptr);
}